// round 16
// baseline (speedup 1.0000x reference)
#include <cuda_runtime.h>
#include <cuda_fp16.h>
#include <math.h>

#define BB 1024
#define TT 512
#define II 4
#define HH 32
#define GG 96   // 3*H

typedef unsigned long long u64;

// Scratch sequence buffers (allocation-free rule: __device__ globals).
__device__ __half g_h1 [(size_t)BB * TT * 2 * HH];   // layer0 out (fp16)
__device__ u64    g_xg [(size_t)2 * BB * TT * HH];   // layer1 gates packed (r,z,n,pad)
__device__ __half g_out[(size_t)BB * TT * 2 * HH];   // layer1 out (fp16)

// HW tanh: single MUFU op
__device__ __forceinline__ float ftanh(float x) {
    float y;
    asm("tanh.approx.f32 %0, %1;" : "=f"(y) : "f"(x));
    return y;
}
// sigmoid(x) = 0.5*tanh(0.5x) + 0.5
__device__ __forceinline__ float fsig(float x) {
    return fmaf(0.5f, ftanh(0.5f * x), 0.5f);
}
__device__ __forceinline__ __half2 u64_to_h2(u64 v) {
    float lo, hi;
    asm("mov.b64 {%0, %1}, %2;" : "=f"(lo), "=f"(hi) : "l"(v));
    return __floats2half2_rn(lo, hi);
}
__device__ __forceinline__ float h2sum(__half2 v) {
    return __low2float(v) + __high2float(v);
}
__device__ __forceinline__ float red4(__half2 a, __half2 b, __half2 c, __half2 d) {
    return h2sum(__hadd2(__hadd2(a, b), __hadd2(c, d)));
}
#define H2(u) (*(const __half2*)&(u))
#define HZERO __floats2half2_rn(0.0f, 0.0f)

// ---------------------------------------------------------------------------
// Layer 0: one warp per (b, dir). HFMA2 MACs (depth-4 chains), fp16 input
// projection, folded r-sigmoid, HW tanh, prefetch depth 2.
// grid: (B/4, 2), block 128.
// ---------------------------------------------------------------------------
__global__ void __launch_bounds__(128) gru_l0(
    const float* __restrict__ x,      // [B,T,4]
    const float* __restrict__ w_ih,   // [2,96,4]
    const float* __restrict__ w_hh,   // [2,96,32]
    const float* __restrict__ b_ih,   // [2,96]
    const float* __restrict__ b_hh)   // [2,96]
{
    __shared__ __align__(16) __half sh[4][2][32];

    const int warp = threadIdx.x >> 5;
    const int j    = threadIdx.x & 31;
    const int dir  = blockIdx.y;
    const int b    = blockIdx.x * 4 + warp;

    const u64* w64 = (const u64*)w_hh;
    __half2 wr[16], wz[16], wn[16];
    {
        const int rb = (dir * GG + j) * 16;
        const int zb = (dir * GG + 32 + j) * 16;
        const int nb = (dir * GG + 64 + j) * 16;
        #pragma unroll
        for (int m = 0; m < 16; m++) {
            wr[m] = u64_to_h2(w64[rb + m]);
            wz[m] = u64_to_h2(w64[zb + m]);
            wn[m] = u64_to_h2(w64[nb + m]);
        }
    }
    // fp16 input-projection weights (rows of 4 floats -> 2 half2)
    const u64* wi64 = (const u64*)w_ih;
    const __half2 wir0 = u64_to_h2(wi64[(dir * GG + j) * 2]);
    const __half2 wir1 = u64_to_h2(wi64[(dir * GG + j) * 2 + 1]);
    const __half2 wiz0 = u64_to_h2(wi64[(dir * GG + 32 + j) * 2]);
    const __half2 wiz1 = u64_to_h2(wi64[(dir * GG + 32 + j) * 2 + 1]);
    const __half2 win0 = u64_to_h2(wi64[(dir * GG + 64 + j) * 2]);
    const __half2 win1 = u64_to_h2(wi64[(dir * GG + 64 + j) * 2 + 1]);

    const float brf = b_ih[dir * GG + j]      + b_hh[dir * GG + j];
    const float bzf = b_ih[dir * GG + 32 + j] + b_hh[dir * GG + 32 + j];
    const float bxn = b_ih[dir * GG + 64 + j];
    const float bhn = b_hh[dir * GG + 64 + j];

    float h = 0.0f;
    const int tstep = dir ? -1 : 1;
    int t = dir ? (TT - 1) : 0;

    const ulonglong2* xb2 = (const ulonglong2*)(x + (size_t)b * TT * II);
    __half* ob = g_h1 + (size_t)b * TT * 2 * HH + dir * HH + j;

    // prefetch queue depth 2, converted to fp16 at prefetch time
    ulonglong2 raw;
    raw = xb2[t];
    __half2 x0a = u64_to_h2(raw.x), x0b = u64_to_h2(raw.y);
    raw = xb2[t + tstep];
    __half2 x1a = u64_to_h2(raw.x), x1b = u64_to_h2(raw.y);

    for (int s = 0; s < TT; ++s, t += tstep) {
        int tp = t + 2 * tstep;
        tp = (tp < 0) ? 0 : ((tp >= TT) ? (TT - 1) : tp);
        raw = xb2[tp];
        const __half2 x2a = u64_to_h2(raw.x), x2b = u64_to_h2(raw.y);

        const int par = s & 1;
        sh[warp][par][j] = __float2half(h);
        __syncwarp();

        // depth-4 chains per gate; r/z input proj folds into chains 0/1,
        // n input proj kept separate (must not be scaled by r)
        __half2 rc0 = __hfma2(wir0, x0a, HZERO), rc1 = __hfma2(wir1, x0b, HZERO);
        __half2 rc2 = HZERO, rc3 = HZERO;
        __half2 zc0 = __hfma2(wiz0, x0a, HZERO), zc1 = __hfma2(wiz1, x0b, HZERO);
        __half2 zc2 = HZERO, zc3 = HZERO;
        __half2 nc0 = HZERO, nc1 = HZERO, nc2 = HZERO, nc3 = HZERO;
        const __half2 xn2 = __hfma2(win0, x0a, __hfma2(win1, x0b, HZERO));

        const uint4* hv = (const uint4*)sh[warp][par];
        #pragma unroll
        for (int q = 0; q < 4; q++) {
            const uint4 u = hv[q];
            rc0 = __hfma2(wr[4 * q],     H2(u.x), rc0);
            zc0 = __hfma2(wz[4 * q],     H2(u.x), zc0);
            nc0 = __hfma2(wn[4 * q],     H2(u.x), nc0);
            rc1 = __hfma2(wr[4 * q + 1], H2(u.y), rc1);
            zc1 = __hfma2(wz[4 * q + 1], H2(u.y), zc1);
            nc1 = __hfma2(wn[4 * q + 1], H2(u.y), nc1);
            rc2 = __hfma2(wr[4 * q + 2], H2(u.z), rc2);
            zc2 = __hfma2(wz[4 * q + 2], H2(u.z), zc2);
            nc2 = __hfma2(wn[4 * q + 2], H2(u.z), nc2);
            rc3 = __hfma2(wr[4 * q + 3], H2(u.w), rc3);
            zc3 = __hfma2(wz[4 * q + 3], H2(u.w), zc3);
            nc3 = __hfma2(wn[4 * q + 3], H2(u.w), nc3);
        }

        const float sr = brf + red4(rc0, rc1, rc2, rc3);
        const float sz = bzf + red4(zc0, zc1, zc2, zc3);
        const float B  = bhn + red4(nc0, nc1, nc2, nc3);

        const float tr    = ftanh(0.5f * sr);
        const float z     = fsig(sz);
        const float halfB = 0.5f * B;
        const float base  = bxn + h2sum(xn2) + halfB;
        const float n     = ftanh(fmaf(halfB, tr, base));
        h = n + z * (h - n);

        ob[(size_t)t * 2 * HH] = __float2half(h);
        x0a = x1a; x0b = x1b;
        x1a = x2a; x1b = x2b;
    }
}

// ---------------------------------------------------------------------------
// Layer 1 input projection, packed u64 gate output. block 128, grid 1024.
// ---------------------------------------------------------------------------
__global__ void __launch_bounds__(128) gru_l1_xg(
    const float* __restrict__ w_ih,   // [2,96,64]
    const float* __restrict__ b_ih)   // [2,96]
{
    __shared__ __align__(16) unsigned int sx[4][2][2][32];

    const int w = threadIdx.x >> 5;
    const int j = threadIdx.x & 31;

    const int task  = blockIdx.x * 4 + w;   // (b*2 + dir)*2 + chunkhalf
    const int chalf = task & 1;
    const int bd    = task >> 1;
    const int dir   = bd & 1;
    const int b     = bd >> 1;

    const u64* w64 = (const u64*)w_ih;
    __half2 wgr[32], wgz[32], wgn[32];
    {
        const int rb = (dir * GG + j) * 32;
        const int zb = (dir * GG + 32 + j) * 32;
        const int nb = (dir * GG + 64 + j) * 32;
        #pragma unroll
        for (int m = 0; m < 32; m++) {
            wgr[m] = u64_to_h2(w64[rb + m]);
            wgz[m] = u64_to_h2(w64[zb + m]);
            wgn[m] = u64_to_h2(w64[nb + m]);
        }
    }
    const float br = b_ih[dir * GG + j];
    const float bz = b_ih[dir * GG + 32 + j];
    const float bn = b_ih[dir * GG + 64 + j];

    const unsigned int* ib = (const unsigned int*)g_h1 + (size_t)b * TT * 32;
    u64* xo = g_xg + ((size_t)(dir * BB + b) * TT) * 32 + j;

    const int t0 = chalf * (TT / 2);
    unsigned int a0 = ib[(size_t)t0 * 32 + j];
    unsigned int a1 = ib[(size_t)(t0 + 1) * 32 + j];

    for (int s = 0; s < TT / 4; ++s) {
        const int t  = t0 + 2 * s;
        const int tn = (s == TT / 4 - 1) ? t : (t + 2);
        const unsigned int p0 = ib[(size_t)tn * 32 + j];
        const unsigned int p1 = ib[(size_t)(tn + 1) * 32 + j];

        const int par = s & 1;
        sx[w][par][0][j] = a0;
        sx[w][par][1][j] = a1;
        __syncwarp();

        __half2 R0, R1, Z0, Z1, N0, N1;
        __half2 R2, R3, Z2, Z3, N2, N3;
        R0 = R1 = Z0 = Z1 = N0 = N1 = HZERO;
        R2 = R3 = Z2 = Z3 = N2 = N3 = HZERO;

        const uint4* r0p = (const uint4*)&sx[w][par][0][0];
        const uint4* r1p = (const uint4*)&sx[w][par][1][0];
        #pragma unroll
        for (int q = 0; q < 8; q++) {
            const uint4 u = r0p[q];
            const uint4 v = r1p[q];
            R0 = __hfma2(wgr[4 * q],     H2(u.x), R0);
            Z0 = __hfma2(wgz[4 * q],     H2(u.x), Z0);
            N0 = __hfma2(wgn[4 * q],     H2(u.x), N0);
            R1 = __hfma2(wgr[4 * q + 1], H2(u.y), R1);
            Z1 = __hfma2(wgz[4 * q + 1], H2(u.y), Z1);
            N1 = __hfma2(wgn[4 * q + 1], H2(u.y), N1);
            R0 = __hfma2(wgr[4 * q + 2], H2(u.z), R0);
            Z0 = __hfma2(wgz[4 * q + 2], H2(u.z), Z0);
            N0 = __hfma2(wgn[4 * q + 2], H2(u.z), N0);
            R1 = __hfma2(wgr[4 * q + 3], H2(u.w), R1);
            Z1 = __hfma2(wgz[4 * q + 3], H2(u.w), Z1);
            N1 = __hfma2(wgn[4 * q + 3], H2(u.w), N1);

            R2 = __hfma2(wgr[4 * q],     H2(v.x), R2);
            Z2 = __hfma2(wgz[4 * q],     H2(v.x), Z2);
            N2 = __hfma2(wgn[4 * q],     H2(v.x), N2);
            R3 = __hfma2(wgr[4 * q + 1], H2(v.y), R3);
            Z3 = __hfma2(wgz[4 * q + 1], H2(v.y), Z3);
            N3 = __hfma2(wgn[4 * q + 1], H2(v.y), N3);
            R2 = __hfma2(wgr[4 * q + 2], H2(v.z), R2);
            Z2 = __hfma2(wgz[4 * q + 2], H2(v.z), Z2);
            N2 = __hfma2(wgn[4 * q + 2], H2(v.z), N2);
            R3 = __hfma2(wgr[4 * q + 3], H2(v.w), R3);
            Z3 = __hfma2(wgz[4 * q + 3], H2(v.w), Z3);
            N3 = __hfma2(wgn[4 * q + 3], H2(v.w), N3);
        }

        {
            const float rv = br + h2sum(__hadd2(R0, R1));
            const float zv = bz + h2sum(__hadd2(Z0, Z1));
            const float nv = bn + h2sum(__hadd2(N0, N1));
            const __half2 lo = __floats2half2_rn(rv, zv);
            const __half2 hi = __floats2half2_rn(nv, 0.0f);
            u64 pk;
            asm("mov.b64 %0, {%1, %2};" : "=l"(pk)
                : "r"(*(const unsigned int*)&lo), "r"(*(const unsigned int*)&hi));
            xo[(size_t)t * 32] = pk;
        }
        {
            const float rv = br + h2sum(__hadd2(R2, R3));
            const float zv = bz + h2sum(__hadd2(Z2, Z3));
            const float nv = bn + h2sum(__hadd2(N2, N3));
            const __half2 lo = __floats2half2_rn(rv, zv);
            const __half2 hi = __floats2half2_rn(nv, 0.0f);
            u64 pk;
            asm("mov.b64 %0, {%1, %2};" : "=l"(pk)
                : "r"(*(const unsigned int*)&lo), "r"(*(const unsigned int*)&hi));
            xo[(size_t)(t + 1) * 32] = pk;
        }
        a0 = p0; a1 = p1;
    }
}

// ---------------------------------------------------------------------------
// Layer 1 recurrence: single u64 gate load/step, prefetch depth 3, depth-4
// chains, folded r-sigmoid, HW tanh, fp16 output. grid (B/4, 2), block 128.
// ---------------------------------------------------------------------------
__global__ void __launch_bounds__(128) gru_l1_rec(
    const float* __restrict__ w_hh,   // [2,96,32]
    const float* __restrict__ b_hh)   // [2,96]
{
    __shared__ __align__(16) __half sh[4][2][32];

    const int warp = threadIdx.x >> 5;
    const int j    = threadIdx.x & 31;
    const int dir  = blockIdx.y;
    const int b    = blockIdx.x * 4 + warp;

    const u64* w64 = (const u64*)w_hh;
    __half2 wr[16], wz[16], wn[16];
    {
        const int rb = (dir * GG + j) * 16;
        const int zb = (dir * GG + 32 + j) * 16;
        const int nb = (dir * GG + 64 + j) * 16;
        #pragma unroll
        for (int m = 0; m < 16; m++) {
            wr[m] = u64_to_h2(w64[rb + m]);
            wz[m] = u64_to_h2(w64[zb + m]);
            wn[m] = u64_to_h2(w64[nb + m]);
        }
    }
    const float brh = b_hh[dir * GG + j];
    const float bzh = b_hh[dir * GG + 32 + j];
    const float bhn = b_hh[dir * GG + 64 + j];

    float h = 0.0f;
    const int tstep = dir ? -1 : 1;
    int t = dir ? (TT - 1) : 0;

    const u64* xgb = g_xg + ((size_t)(dir * BB + b) * TT) * 32 + j;
    __half* ob = g_out + (size_t)b * TT * 2 * HH + dir * HH + j;

    u64 q0 = xgb[(size_t)t * 32];
    u64 q1 = xgb[(size_t)(t + tstep) * 32];
    u64 q2 = xgb[(size_t)(t + 2 * tstep) * 32];

    for (int s = 0; s < TT; ++s, t += tstep) {
        int tp = t + 3 * tstep;
        tp = (tp < 0) ? 0 : ((tp >= TT) ? (TT - 1) : tp);
        const u64 q3 = xgb[(size_t)tp * 32];

        const int par = s & 1;
        sh[warp][par][j] = __float2half(h);
        __syncwarp();

        unsigned int lo_u, hi_u;
        asm("mov.b64 {%0, %1}, %2;" : "=r"(lo_u), "=r"(hi_u) : "l"(q0));
        const float xr = __low2float(H2(lo_u));
        const float xz = __high2float(H2(lo_u));
        const float xn = __low2float(H2(hi_u));

        __half2 rc0 = HZERO, rc1 = HZERO, rc2 = HZERO, rc3 = HZERO;
        __half2 zc0 = HZERO, zc1 = HZERO, zc2 = HZERO, zc3 = HZERO;
        __half2 nc0 = HZERO, nc1 = HZERO, nc2 = HZERO, nc3 = HZERO;

        const uint4* hv = (const uint4*)sh[warp][par];
        #pragma unroll
        for (int q = 0; q < 4; q++) {
            const uint4 u = hv[q];
            rc0 = __hfma2(wr[4 * q],     H2(u.x), rc0);
            zc0 = __hfma2(wz[4 * q],     H2(u.x), zc0);
            nc0 = __hfma2(wn[4 * q],     H2(u.x), nc0);
            rc1 = __hfma2(wr[4 * q + 1], H2(u.y), rc1);
            zc1 = __hfma2(wz[4 * q + 1], H2(u.y), zc1);
            nc1 = __hfma2(wn[4 * q + 1], H2(u.y), nc1);
            rc2 = __hfma2(wr[4 * q + 2], H2(u.z), rc2);
            zc2 = __hfma2(wz[4 * q + 2], H2(u.z), zc2);
            nc2 = __hfma2(wn[4 * q + 2], H2(u.z), nc2);
            rc3 = __hfma2(wr[4 * q + 3], H2(u.w), rc3);
            zc3 = __hfma2(wz[4 * q + 3], H2(u.w), zc3);
            nc3 = __hfma2(wn[4 * q + 3], H2(u.w), nc3);
        }

        const float sr = xr + brh + red4(rc0, rc1, rc2, rc3);
        const float sz = xz + bzh + red4(zc0, zc1, zc2, zc3);
        const float B  = bhn + red4(nc0, nc1, nc2, nc3);

        const float tr    = ftanh(0.5f * sr);
        const float z     = fsig(sz);
        const float halfB = 0.5f * B;
        const float base  = xn + halfB;
        const float n     = ftanh(fmaf(halfB, tr, base));
        h = n + z * (h - n);

        ob[(size_t)t * 2 * HH] = __float2half(h);
        q0 = q1; q1 = q2; q2 = q3;
    }
}

// ---------------------------------------------------------------------------
// Epilogue: single-pass online-softmax attention pooling + sigmoid FC.
// g_out is fp16: lane reads one half2 (dims 2l, 2l+1) per row.
// ---------------------------------------------------------------------------
__global__ void __launch_bounds__(256) attn_fc_kernel(
    const float* __restrict__ attn_w,  // [1,64]
    const float* __restrict__ fc_w,    // [1,64]
    const float* __restrict__ fc_b,    // [1]
    float* __restrict__ y)             // [B,1]
{
    __shared__ float saw[64], sfw[64];
    __shared__ float sm[8], sz[8];
    __shared__ float sctx[8][64];

    const int b    = blockIdx.x;
    const int tid  = threadIdx.x;
    const int warp = tid >> 5;
    const int lane = tid & 31;

    if (tid < 64) {
        saw[tid] = attn_w[tid];
        sfw[tid] = fc_w[tid];
    }
    __syncthreads();

    const float aw0 = saw[2 * lane], aw1 = saw[2 * lane + 1];
    const unsigned int* ob = (const unsigned int*)g_out + (size_t)b * TT * 32;

    float m = -INFINITY, Z = 0.0f, c0 = 0.0f, c1 = 0.0f;
    for (int t = warp; t < TT; t += 8) {
        const unsigned int u = ob[(size_t)t * 32 + lane];
        const float q0 = __low2float(H2(u));
        const float q1 = __high2float(H2(u));
        float v = q0 * aw0 + q1 * aw1;
        #pragma unroll
        for (int o = 16; o; o >>= 1) v += __shfl_xor_sync(0xffffffffu, v, o);
        const float mn = fmaxf(m, v);
        const float sc = __expf(m - mn);
        const float e  = __expf(v - mn);
        Z  = Z * sc + e;
        c0 = c0 * sc + e * q0;
        c1 = c1 * sc + e * q1;
        m = mn;
    }
    if (lane == 0) sm[warp] = m;
    __syncthreads();

    float M = sm[0];
    #pragma unroll
    for (int w = 1; w < 8; w++) M = fmaxf(M, sm[w]);
    const float sc = __expf(m - M);
    if (lane == 0) sz[warp] = Z * sc;
    sctx[warp][2 * lane]     = c0 * sc;
    sctx[warp][2 * lane + 1] = c1 * sc;
    __syncthreads();

    if (tid < 32) {
        float Zt = 0.0f, C0 = 0.0f, C1 = 0.0f;
        #pragma unroll
        for (int w = 0; w < 8; w++) {
            Zt += sz[w];
            C0 += sctx[w][2 * lane];
            C1 += sctx[w][2 * lane + 1];
        }
        float v = C0 * sfw[2 * lane] + C1 * sfw[2 * lane + 1];
        #pragma unroll
        for (int o = 16; o; o >>= 1) v += __shfl_xor_sync(0xffffffffu, v, o);
        if (lane == 0) {
            y[b] = fmaf(0.5f, ftanh(0.5f * (__fdividef(v, Zt) + fc_b[0])), 0.5f);
        }
    }
}

extern "C" void kernel_launch(void* const* d_in, const int* in_sizes, int n_in,
                              void* d_out, int out_size) {
    const float* x       = (const float*)d_in[0];
    const float* w_ih_l0 = (const float*)d_in[1];
    const float* w_hh_l0 = (const float*)d_in[2];
    const float* b_ih_l0 = (const float*)d_in[3];
    const float* b_hh_l0 = (const float*)d_in[4];
    const float* w_ih_l1 = (const float*)d_in[5];
    const float* w_hh_l1 = (const float*)d_in[6];
    const float* b_ih_l1 = (const float*)d_in[7];
    const float* b_hh_l1 = (const float*)d_in[8];
    const float* attn_w  = (const float*)d_in[9];
    // d_in[10] = attn_b (cancels in softmax)
    const float* fc_w    = (const float*)d_in[11];
    const float* fc_b    = (const float*)d_in[12];
    float* y = (float*)d_out;

    gru_l0    <<<dim3(BB / 4, 2), 128>>>(x, w_ih_l0, w_hh_l0, b_ih_l0, b_hh_l0);
    gru_l1_xg <<<(BB * 2 * 2) / 4, 128>>>(w_ih_l1, b_ih_l1);
    gru_l1_rec<<<dim3(BB / 4, 2), 128>>>(w_hh_l1, b_hh_l1);
    attn_fc_kernel<<<BB, 256>>>(attn_w, fc_w, fc_b, y);
}